// round 1
// baseline (speedup 1.0000x reference)
#include <cuda_runtime.h>
#include <math.h>

#define B_ 8
#define T_ 1024
#define F_ 512
#define H_ 8
#define DK_ 64
#define P_ 2047

// -------- scratch (device globals; no allocations allowed) --------
__device__ float g_Q[(size_t)B_ * T_ * F_];          // 16 MB
__device__ float g_K[(size_t)B_ * T_ * F_];          // 16 MB
__device__ float g_V[(size_t)B_ * T_ * F_];          // 16 MB
__device__ float g_P[(size_t)(P_ + 1) * F_];         // ~4 MB
__device__ float g_S[(size_t)B_ * H_ * T_ * T_];     // 256 MB
__device__ float g_ctx[(size_t)B_ * T_ * F_];        // 16 MB

// =====================================================================
// Generic NT GEMM:  C[M,N] = A[M,K] @ W[N,K]^T (+ bias[N])
// 128x128 block tile, BK=16, 256 threads, 8x8 per thread.
// =====================================================================
__global__ void __launch_bounds__(256) gemm_nt_bias(
    const float* __restrict__ A, const float* __restrict__ W,
    const float* __restrict__ bias, float* __restrict__ C,
    int M, int N, int K)
{
    __shared__ __align__(16) float As[16][132];  // [k][m]
    __shared__ __align__(16) float Ws[16][132];  // [k][n]

    const int tid = threadIdx.x;
    const int tx = tid & 15;   // n direction
    const int ty = tid >> 4;   // m direction
    const int m0 = blockIdx.y * 128;
    const int n0 = blockIdx.x * 128;

    float acc[8][8];
#pragma unroll
    for (int i = 0; i < 8; i++)
#pragma unroll
        for (int j = 0; j < 8; j++) acc[i][j] = 0.f;

    for (int k0 = 0; k0 < K; k0 += 16) {
#pragma unroll
        for (int f = tid; f < 512; f += 256) {
            int r = f >> 2;
            int c = (f & 3) << 2;
            int gm = m0 + r; if (gm >= M) gm = M - 1;
            float4 a4 = *(const float4*)(A + (size_t)gm * K + k0 + c);
            As[c + 0][r] = a4.x; As[c + 1][r] = a4.y;
            As[c + 2][r] = a4.z; As[c + 3][r] = a4.w;
            int gn = n0 + r; if (gn >= N) gn = N - 1;
            float4 w4 = *(const float4*)(W + (size_t)gn * K + k0 + c);
            Ws[c + 0][r] = w4.x; Ws[c + 1][r] = w4.y;
            Ws[c + 2][r] = w4.z; Ws[c + 3][r] = w4.w;
        }
        __syncthreads();

#pragma unroll
        for (int kk = 0; kk < 16; kk++) {
            float4 ra0 = *(const float4*)&As[kk][ty * 8];
            float4 ra1 = *(const float4*)&As[kk][ty * 8 + 4];
            float4 rb0 = *(const float4*)&Ws[kk][tx * 8];
            float4 rb1 = *(const float4*)&Ws[kk][tx * 8 + 4];
            float ra[8] = {ra0.x, ra0.y, ra0.z, ra0.w, ra1.x, ra1.y, ra1.z, ra1.w};
            float rb[8] = {rb0.x, rb0.y, rb0.z, rb0.w, rb1.x, rb1.y, rb1.z, rb1.w};
#pragma unroll
            for (int i = 0; i < 8; i++)
#pragma unroll
                for (int j = 0; j < 8; j++)
                    acc[i][j] = fmaf(ra[i], rb[j], acc[i][j]);
        }
        __syncthreads();
    }

#pragma unroll
    for (int i = 0; i < 8; i++) {
        int gm = m0 + ty * 8 + i;
        if (gm >= M) continue;
#pragma unroll
        for (int j = 0; j < 8; j++) {
            int gn = n0 + tx * 8 + j;
            if (gn >= N) continue;
            float bv = bias ? bias[gn] : 0.f;
            C[(size_t)gm * N + gn] = acc[i][j] + bv;
        }
    }
}

// =====================================================================
// Fused scores:  S[b,h,t,s] = ( (q+u)·k[s] + (q+v)·p[T-1-t+s] ) / sqrt(DK)
// rel_shift folded into the p index. 64x64 tile per block, 4x4 / thread.
// =====================================================================
__global__ void __launch_bounds__(256) scores_kernel(
    const float* __restrict__ pu, const float* __restrict__ pv)
{
    __shared__ float qu[64][33];
    __shared__ float qv[64][33];
    __shared__ float ks[64][33];
    __shared__ float pw[127][33];

    const int tid = threadIdx.x;
    const int tx = tid & 15;   // s direction
    const int ty = tid >> 4;   // t direction
    const int bh = blockIdx.z;
    const int b = bh >> 3;
    const int h = bh & 7;
    const int t0 = blockIdx.y * 64;
    const int s0 = blockIdx.x * 64;
    const int rbase = (T_ - 1) - t0 - 63 + s0;  // >= 0, rbase+126 <= 2046
    const int base = 60 + tx * 4 - ty * 4;      // pw row offset index base

    float accA[4][4], accB[4][4];
#pragma unroll
    for (int i = 0; i < 4; i++)
#pragma unroll
        for (int j = 0; j < 4; j++) { accA[i][j] = 0.f; accB[i][j] = 0.f; }

    for (int dc = 0; dc < DK_; dc += 32) {
        // load q (make qu/qv), k tiles: 64 rows x 32 cols each
        for (int e = tid; e < 512; e += 256) {
            int r = e >> 3;
            int c = (e & 7) << 2;
            float4 q4 = *(const float4*)(g_Q + ((size_t)(b * T_ + t0 + r)) * F_ + h * DK_ + dc + c);
            float4 u4 = *(const float4*)(pu + h * DK_ + dc + c);
            float4 v4 = *(const float4*)(pv + h * DK_ + dc + c);
            qu[r][c + 0] = q4.x + u4.x; qu[r][c + 1] = q4.y + u4.y;
            qu[r][c + 2] = q4.z + u4.z; qu[r][c + 3] = q4.w + u4.w;
            qv[r][c + 0] = q4.x + v4.x; qv[r][c + 1] = q4.y + v4.y;
            qv[r][c + 2] = q4.z + v4.z; qv[r][c + 3] = q4.w + v4.w;
            float4 k4 = *(const float4*)(g_K + ((size_t)(b * T_ + s0 + r)) * F_ + h * DK_ + dc + c);
            ks[r][c + 0] = k4.x; ks[r][c + 1] = k4.y;
            ks[r][c + 2] = k4.z; ks[r][c + 3] = k4.w;
        }
        // load p window: 127 rows x 32 cols
        for (int e = tid; e < 1016; e += 256) {
            int r = e >> 3;
            int c = (e & 7) << 2;
            float4 p4 = *(const float4*)(g_P + (size_t)(rbase + r) * F_ + h * DK_ + dc + c);
            pw[r][c + 0] = p4.x; pw[r][c + 1] = p4.y;
            pw[r][c + 2] = p4.z; pw[r][c + 3] = p4.w;
        }
        __syncthreads();

#pragma unroll 8
        for (int d = 0; d < 32; d++) {
            float a[4], bb[4], kr[4], pr[7];
#pragma unroll
            for (int i = 0; i < 4; i++) {
                a[i] = qu[ty * 4 + i][d];
                bb[i] = qv[ty * 4 + i][d];
            }
#pragma unroll
            for (int j = 0; j < 4; j++) kr[j] = ks[tx * 4 + j][d];
#pragma unroll
            for (int m = 0; m < 7; m++) pr[m] = pw[base + m][d];
#pragma unroll
            for (int i = 0; i < 4; i++)
#pragma unroll
                for (int j = 0; j < 4; j++) {
                    accA[i][j] = fmaf(a[i], kr[j], accA[i][j]);
                    accB[i][j] = fmaf(bb[i], pr[j - i + 3], accB[i][j]);
                }
        }
        __syncthreads();
    }

#pragma unroll
    for (int i = 0; i < 4; i++) {
        size_t row = ((size_t)bh * T_ + t0 + ty * 4 + i) * T_ + s0 + tx * 4;
        float4 o;
        o.x = (accA[i][0] + accB[i][0]) * 0.125f;
        o.y = (accA[i][1] + accB[i][1]) * 0.125f;
        o.z = (accA[i][2] + accB[i][2]) * 0.125f;
        o.w = (accA[i][3] + accB[i][3]) * 0.125f;
        *(float4*)(g_S + row) = o;
    }
}

// =====================================================================
// Masked softmax over last dim (T=1024). One block per row, 256 threads.
// =====================================================================
__global__ void __launch_bounds__(256) softmax_kernel(const int* __restrict__ mask)
{
    const int row = blockIdx.x;           // bh*T + t
    const int b = row >> 13;              // / (H*T)
    float* srow = g_S + (size_t)row * T_;
    const int* mrow = mask + b * T_;

    __shared__ float red[8];
    const int tid = threadIdx.x;
    const int lane = tid & 31;
    const int warp = tid >> 5;
    const float NEG = -3.402823466e38f;

    float vals[4];
    float mx = NEG;
#pragma unroll
    for (int q = 0; q < 4; q++) {
        int s = tid + q * 256;
        float x = srow[s];
        if (mrow[s] == 0) x = NEG;
        vals[q] = x;
        mx = fmaxf(mx, x);
    }
#pragma unroll
    for (int o = 16; o > 0; o >>= 1) mx = fmaxf(mx, __shfl_xor_sync(0xffffffffu, mx, o));
    if (lane == 0) red[warp] = mx;
    __syncthreads();
    float mall = red[0];
#pragma unroll
    for (int w = 1; w < 8; w++) mall = fmaxf(mall, red[w]);
    __syncthreads();

    float sum = 0.f;
#pragma unroll
    for (int q = 0; q < 4; q++) {
        float e = __expf(vals[q] - mall);
        vals[q] = e;
        sum += e;
    }
#pragma unroll
    for (int o = 16; o > 0; o >>= 1) sum += __shfl_xor_sync(0xffffffffu, sum, o);
    if (lane == 0) red[warp] = sum;
    __syncthreads();
    float tot = red[0];
#pragma unroll
    for (int w = 1; w < 8; w++) tot += red[w];
    float inv = 1.f / tot;

#pragma unroll
    for (int q = 0; q < 4; q++) {
        int s = tid + q * 256;
        float o = vals[q] * inv;
        if (mrow[s] == 0) o = 0.f;
        srow[s] = o;
    }
}

// =====================================================================
// ctx[b,t,h*64+d] = sum_s attn[b,h,t,s] * V[b,s,h*64+d]
// 64 (t) x 64 (d) tile per block, s in chunks of 64. 4x4 per thread.
// =====================================================================
__global__ void __launch_bounds__(256) av_kernel()
{
    __shared__ __align__(16) float as[64][68];
    __shared__ __align__(16) float vs[64][68];

    const int tid = threadIdx.x;
    const int tx = tid & 15;   // d direction
    const int ty = tid >> 4;   // t direction
    const int bh = blockIdx.y;
    const int b = bh >> 3;
    const int h = bh & 7;
    const int t0 = blockIdx.x * 64;

    float acc[4][4];
#pragma unroll
    for (int i = 0; i < 4; i++)
#pragma unroll
        for (int j = 0; j < 4; j++) acc[i][j] = 0.f;

    for (int s0 = 0; s0 < T_; s0 += 64) {
        for (int f = tid; f < 1024; f += 256) {
            int r = f >> 4;
            int c = (f & 15) << 2;
            *(float4*)&as[r][c] =
                *(const float4*)(g_S + ((size_t)bh * T_ + t0 + r) * T_ + s0 + c);
            *(float4*)&vs[r][c] =
                *(const float4*)(g_V + ((size_t)(b * T_ + s0 + r)) * F_ + h * DK_ + c);
        }
        __syncthreads();

#pragma unroll 4
        for (int s4 = 0; s4 < 64; s4 += 4) {
            float aa[4][4], av[4][4];
#pragma unroll
            for (int i = 0; i < 4; i++) {
                float4 t4 = *(const float4*)&as[ty * 4 + i][s4];
                aa[i][0] = t4.x; aa[i][1] = t4.y; aa[i][2] = t4.z; aa[i][3] = t4.w;
            }
#pragma unroll
            for (int q = 0; q < 4; q++) {
                float4 t4 = *(const float4*)&vs[s4 + q][tx * 4];
                av[q][0] = t4.x; av[q][1] = t4.y; av[q][2] = t4.z; av[q][3] = t4.w;
            }
#pragma unroll
            for (int i = 0; i < 4; i++)
#pragma unroll
                for (int j = 0; j < 4; j++) {
                    acc[i][j] = fmaf(aa[i][0], av[0][j], acc[i][j]);
                    acc[i][j] = fmaf(aa[i][1], av[1][j], acc[i][j]);
                    acc[i][j] = fmaf(aa[i][2], av[2][j], acc[i][j]);
                    acc[i][j] = fmaf(aa[i][3], av[3][j], acc[i][j]);
                }
        }
        __syncthreads();
    }

#pragma unroll
    for (int i = 0; i < 4; i++) {
        size_t row = ((size_t)(b * T_ + t0 + ty * 4 + i)) * F_ + h * DK_ + tx * 4;
        float4 o;
        o.x = acc[i][0]; o.y = acc[i][1]; o.z = acc[i][2]; o.w = acc[i][3];
        *(float4*)(g_ctx + row) = o;
    }
}

// =====================================================================
extern "C" void kernel_launch(void* const* d_in, const int* in_sizes, int n_in,
                              void* d_out, int out_size)
{
    const float* query   = (const float*)d_in[0];
    const float* key_in  = (const float*)d_in[1];
    const float* value   = (const float*)d_in[2];
    const float* pos_emb = (const float*)d_in[3];
    const int*   mask    = (const int*)d_in[4];
    const float* Wq = (const float*)d_in[5];
    const float* bq = (const float*)d_in[6];
    const float* Wk = (const float*)d_in[7];
    const float* bk = (const float*)d_in[8];
    const float* Wv = (const float*)d_in[9];
    const float* bv = (const float*)d_in[10];
    const float* Wo = (const float*)d_in[11];
    const float* bo = (const float*)d_in[12];
    const float* Wp = (const float*)d_in[13];
    const float* pu = (const float*)d_in[14];
    const float* pv = (const float*)d_in[15];
    float* out = (float*)d_out;

    float *Qp, *Kp, *Vp, *Pq, *Cp;
    cudaGetSymbolAddress((void**)&Qp, g_Q);
    cudaGetSymbolAddress((void**)&Kp, g_K);
    cudaGetSymbolAddress((void**)&Vp, g_V);
    cudaGetSymbolAddress((void**)&Pq, g_P);
    cudaGetSymbolAddress((void**)&Cp, g_ctx);

    dim3 blk(256);

    // projections: [8192,512] @ [512,512]^T
    gemm_nt_bias<<<dim3(4, 64), blk>>>(query,  Wq, bq, Qp, B_ * T_, F_, F_);
    gemm_nt_bias<<<dim3(4, 64), blk>>>(key_in, Wk, bk, Kp, B_ * T_, F_, F_);
    gemm_nt_bias<<<dim3(4, 64), blk>>>(value,  Wv, bv, Vp, B_ * T_, F_, F_);
    // positional projection: [2047,512] @ [512,512]^T (no bias)
    gemm_nt_bias<<<dim3(4, 16), blk>>>(pos_emb, Wp, nullptr, Pq, P_, F_, F_);

    // fused AC + rel-shifted BD scores
    scores_kernel<<<dim3(16, 16, B_ * H_), blk>>>(pu, pv);

    // masked softmax
    softmax_kernel<<<dim3(B_ * H_ * T_), blk>>>(mask);

    // attn @ V
    av_kernel<<<dim3(16, B_ * H_), blk>>>();

    // output projection
    gemm_nt_bias<<<dim3(4, 64), blk>>>(Cp, Wo, bo, out, B_ * T_, F_, F_);
}